// round 8
// baseline (speedup 1.0000x reference)
#include <cuda_runtime.h>
#include <cuda_bf16.h>
#include <cuda_fp16.h>
#include <math.h>
#include <stdint.h>

// Problem constants
#define NTOK  43520        // B * LQ
#define LQ_   21760
#define C_    256
#define NHEAD_ 8
#define FF_   1024
#define NL_   6

// ---------------------------------------------------------------------------
// Scratch (static device allocations; no cudaMalloc anywhere)
// ---------------------------------------------------------------------------
__device__ float g_x   [NTOK * C_];
__device__ float g_xp  [NTOK * C_];
__device__ float g_aout[NTOK * C_];
__device__ float g_tmp [NTOK * C_];
__device__ float g_h   [NTOK * FF_];
__device__ __half g_vh [NTOK * C_];        // value proj, fp16 (gather source)
__device__ float g_oa  [NTOK * 384];       // off (256) + att logits (128), fused

// pre-split weights, all layers: [N,K] bf16 hi/lo
__device__ __align__(16) __nv_bfloat16 g_wcat_h[NL_ * 640 * 256];
__device__ __align__(16) __nv_bfloat16 g_wcat_l[NL_ * 640 * 256];
__device__ __align__(16) __nv_bfloat16 g_wo_h  [NL_ * 256 * 256];
__device__ __align__(16) __nv_bfloat16 g_wo_l  [NL_ * 256 * 256];
__device__ __align__(16) __nv_bfloat16 g_w1_h  [NL_ * 1024 * 256];
__device__ __align__(16) __nv_bfloat16 g_w1_l  [NL_ * 1024 * 256];
__device__ __align__(16) __nv_bfloat16 g_w2_h  [NL_ * 256 * 1024];
__device__ __align__(16) __nv_bfloat16 g_w2_l  [NL_ * 256 * 1024];
__device__ float g_bcat[NL_ * 640];

// ---------------------------------------------------------------------------
// PTX helpers (sm_103 base target: mma.sync / ldmatrix / cp.async only)
// ---------------------------------------------------------------------------
__device__ __forceinline__ uint32_t smem_u32(const void* p) {
    return (uint32_t)__cvta_generic_to_shared(p);
}
__device__ __forceinline__ void cp_async16(uint32_t saddr, const void* gaddr) {
    asm volatile("cp.async.cg.shared.global [%0], [%1], 16;" :: "r"(saddr), "l"(gaddr));
}
__device__ __forceinline__ void cp_commit() {
    asm volatile("cp.async.commit_group;" ::: "memory");
}
__device__ __forceinline__ void cp_wait0() {
    asm volatile("cp.async.wait_group 0;" ::: "memory");
}
__device__ __forceinline__ void ldsm4(uint32_t* r, uint32_t a) {
    asm volatile("ldmatrix.sync.aligned.m8n8.x4.shared.b16 {%0,%1,%2,%3}, [%4];"
                 : "=r"(r[0]), "=r"(r[1]), "=r"(r[2]), "=r"(r[3]) : "r"(a));
}
__device__ __forceinline__ void ldsm2(uint32_t* r, uint32_t a) {
    asm volatile("ldmatrix.sync.aligned.m8n8.x2.shared.b16 {%0,%1}, [%2];"
                 : "=r"(r[0]), "=r"(r[1]) : "r"(a));
}
__device__ __forceinline__ void mma16816(float* c, const uint32_t* a, const uint32_t* b) {
    asm volatile("mma.sync.aligned.m16n8k16.row.col.f32.bf16.bf16.f32 "
                 "{%0,%1,%2,%3}, {%4,%5,%6,%7}, {%8,%9}, {%0,%1,%2,%3};"
                 : "+f"(c[0]), "+f"(c[1]), "+f"(c[2]), "+f"(c[3])
                 : "r"(a[0]), "r"(a[1]), "r"(a[2]), "r"(a[3]), "r"(b[0]), "r"(b[1]));
}

// ---------------------------------------------------------------------------
// Weight prep: W fp32 [K,N] slice -> Bt_hi/Bt_lo bf16 [N,K] (transpose + split)
// grid (N/32, K/32, NL), block (32,8). Per-layer strides passed in.
// ---------------------------------------------------------------------------
__global__ void prep_w(const float* __restrict__ W, __nv_bfloat16* __restrict__ Bh,
                       __nv_bfloat16* __restrict__ Bl, int K, int N,
                       size_t srcLayerStride, size_t dstLayerStride) {
    const int L = blockIdx.z;
    W  += (size_t)L * srcLayerStride;
    Bh += (size_t)L * dstLayerStride;
    Bl += (size_t)L * dstLayerStride;
    __shared__ float t[32][33];
    int k0 = blockIdx.y * 32, n0 = blockIdx.x * 32;
    for (int i = threadIdx.y; i < 32; i += 8)
        t[i][threadIdx.x] = W[(size_t)(k0 + i) * N + n0 + threadIdx.x];
    __syncthreads();
    for (int i = threadIdx.y; i < 32; i += 8) {
        float x = t[threadIdx.x][i];                 // W[k0+tx][n0+i]
        __nv_bfloat16 h = __float2bfloat16(x);
        float lo = x - __bfloat162float(h);
        size_t o = (size_t)(n0 + i) * K + k0 + threadIdx.x;
        Bh[o] = h;
        Bl[o] = __float2bfloat16(lo);
    }
}

// bias concat: [bv(256) | boff(256) | bat(128)] per layer
__global__ void bias_cat(const float* __restrict__ bv, const float* __restrict__ boff,
                         const float* __restrict__ bat, float* __restrict__ bcat) {
    int idx = blockIdx.x * blockDim.x + threadIdx.x;
    if (idx >= NL_ * 640) return;
    int L = idx / 640, c = idx % 640;
    float v;
    if (c < 256)      v = bv  [L * 256 + c];
    else if (c < 512) v = boff[L * 256 + c - 256];
    else              v = bat [L * 128 + c - 512];
    bcat[idx] = v;
}

// ---------------------------------------------------------------------------
// Split-bf16 HMMA GEMM: C[M,N] = A[M,K](fp32) @ Bt[N,K](bf16 hi/lo)^T + bias
// MODE 0: fp32 out. MODE 1: fp32 out + ReLU.
// MODE 2: split epilogue for the fused projection (N_=640):
//         cols [0,256)  -> fp16 to VH (stride 256)
//         cols [256,640)-> fp32 to OA (stride 384)
// Tile 128x128, BK=32, 256 threads (8 warps 2x4; warp tile 64x32), 2 stages.
// ---------------------------------------------------------------------------
#define OFF_AH 0
#define OFF_AL 10240
#define OFF_BH 20480
#define OFF_BL 30720
#define STAGE_BYTES 40960

template <int MODE>
__global__ __launch_bounds__(256) void gemm_mma(const float* __restrict__ A,
                                                const __nv_bfloat16* __restrict__ Bh,
                                                const __nv_bfloat16* __restrict__ Bl,
                                                const float* __restrict__ bias,
                                                float* __restrict__ C,
                                                __half* __restrict__ VH,
                                                float* __restrict__ OA,
                                                int M, int K, int N_) {
    extern __shared__ char smem[];
    const uint32_t sbase = smem_u32(smem);
    const int tid  = threadIdx.x;
    const int wid  = tid >> 5;
    const int lane = tid & 31;
    const int warpM = wid >> 2;          // 0..1  -> M offset *64
    const int warpN = wid & 3;           // 0..3  -> N offset *32
    const int m0 = blockIdx.y * 128;
    const int n0 = blockIdx.x * 128;

    float acc[4][4][4];
    #pragma unroll
    for (int i = 0; i < 4; i++)
        #pragma unroll
        for (int j = 0; j < 4; j++)
            #pragma unroll
            for (int r = 0; r < 4; r++) acc[i][j][r] = 0.f;

    const int nkt = K >> 5;
    float4 apre[4];

    auto loadA = [&](int kt) {
        #pragma unroll
        for (int i = 0; i < 4; i++) {
            int idx = tid + i * 256;
            int row = idx >> 3;
            int c4  = (idx & 7) << 2;
            apre[i] = *reinterpret_cast<const float4*>(A + (size_t)(m0 + row) * K + kt * 32 + c4);
        }
    };
    auto storeA = [&](char* stage) {
        #pragma unroll
        for (int i = 0; i < 4; i++) {
            int idx = tid + i * 256;
            int row = idx >> 3;
            int c4  = (idx & 7) << 2;
            float4 a4 = apre[i];
            __nv_bfloat162 h01 = __floats2bfloat162_rn(a4.x, a4.y);
            __nv_bfloat162 h23 = __floats2bfloat162_rn(a4.z, a4.w);
            __nv_bfloat162 l01 = __floats2bfloat162_rn(a4.x - __bfloat162float(h01.x),
                                                       a4.y - __bfloat162float(h01.y));
            __nv_bfloat162 l23 = __floats2bfloat162_rn(a4.z - __bfloat162float(h23.x),
                                                       a4.w - __bfloat162float(h23.y));
            int off = row * 80 + c4 * 2;
            *reinterpret_cast<uint2*>(stage + OFF_AH + off) =
                make_uint2(*reinterpret_cast<uint32_t*>(&h01), *reinterpret_cast<uint32_t*>(&h23));
            *reinterpret_cast<uint2*>(stage + OFF_AL + off) =
                make_uint2(*reinterpret_cast<uint32_t*>(&l01), *reinterpret_cast<uint32_t*>(&l23));
        }
    };
    auto loadB = [&](int kt, uint32_t stage_u) {
        #pragma unroll
        for (int i = 0; i < 2; i++) {
            int idx = tid + i * 256;
            int n = idx >> 2;
            int c = idx & 3;
            size_t g = (size_t)(n0 + n) * K + kt * 32 + c * 8;
            uint32_t s = stage_u + n * 80 + c * 16;
            cp_async16(s + OFF_BH, Bh + g);
            cp_async16(s + OFF_BL, Bl + g);
        }
    };
    auto compute = [&](uint32_t stage_u) {
        const int ar = lane & 15;
        const int ak = (lane >> 4) * 8;
        const int bn = lane & 7;
        const int bk = ((lane >> 3) & 1) * 8;
        #pragma unroll
        for (int kk = 0; kk < 32; kk += 16) {
            uint32_t ah[4][4], al[4][4], bh[4][2], bl[4][2];
            #pragma unroll
            for (int i = 0; i < 4; i++) {
                uint32_t a = stage_u + ((warpM * 64 + i * 16 + ar) * 40 + kk + ak) * 2;
                ldsm4(ah[i], a + OFF_AH);
                ldsm4(al[i], a + OFF_AL);
            }
            #pragma unroll
            for (int j = 0; j < 4; j++) {
                uint32_t b = stage_u + ((warpN * 32 + j * 8 + bn) * 40 + kk + bk) * 2;
                ldsm2(bh[j], b + OFF_BH);
                ldsm2(bl[j], b + OFF_BL);
            }
            #pragma unroll
            for (int i = 0; i < 4; i++)
                #pragma unroll
                for (int j = 0; j < 4; j++) {
                    mma16816(acc[i][j], ah[i], bh[j]);
                    mma16816(acc[i][j], ah[i], bl[j]);
                    mma16816(acc[i][j], al[i], bh[j]);
                }
        }
    };

    // prologue
    loadA(0);
    loadB(0, sbase);
    cp_commit();
    storeA(smem);
    cp_wait0();
    __syncthreads();

    // main loop (double buffered)
    for (int kt = 0; kt < nkt; kt++) {
        const uint32_t cur = sbase + (uint32_t)(kt & 1) * STAGE_BYTES;
        char* nstage = smem + ((kt + 1) & 1) * STAGE_BYTES;
        const uint32_t nxt = sbase + (uint32_t)((kt + 1) & 1) * STAGE_BYTES;
        if (kt + 1 < nkt) {
            loadA(kt + 1);
            loadB(kt + 1, nxt);
            cp_commit();
        }
        compute(cur);
        if (kt + 1 < nkt) {
            storeA(nstage);
            cp_wait0();
        }
        __syncthreads();
    }

    // epilogue
    const int tr = lane >> 2;
    const int tc = (lane & 3) * 2;
    #pragma unroll
    for (int i = 0; i < 4; i++) {
        #pragma unroll
        for (int j = 0; j < 4; j++) {
            int row = m0 + warpM * 64 + i * 16 + tr;
            int col = n0 + warpN * 32 + j * 8 + tc;
            float2 bb = *reinterpret_cast<const float2*>(bias + col);
            float2 o0, o1;
            o0.x = acc[i][j][0] + bb.x; o0.y = acc[i][j][1] + bb.y;
            o1.x = acc[i][j][2] + bb.x; o1.y = acc[i][j][3] + bb.y;
            if (MODE == 1) {
                o0.x = fmaxf(o0.x, 0.f); o0.y = fmaxf(o0.y, 0.f);
                o1.x = fmaxf(o1.x, 0.f); o1.y = fmaxf(o1.y, 0.f);
            }
            if (MODE == 2) {
                if (n0 < 256) {   // value columns -> fp16
                    *reinterpret_cast<__half2*>(VH + (size_t)row * 256 + col) =
                        __floats2half2_rn(o0.x, o0.y);
                    *reinterpret_cast<__half2*>(VH + (size_t)(row + 8) * 256 + col) =
                        __floats2half2_rn(o1.x, o1.y);
                } else {          // off/att columns -> fp32, stride 384
                    int co = col - 256;
                    *reinterpret_cast<float2*>(OA + (size_t)row * 384 + co) = o0;
                    *reinterpret_cast<float2*>(OA + (size_t)(row + 8) * 384 + co) = o1;
                }
            } else {
                *reinterpret_cast<float2*>(C + (size_t)row * N_ + col) = o0;
                *reinterpret_cast<float2*>(C + (size_t)(row + 8) * N_ + col) = o1;
            }
        }
    }
}

// ---------------------------------------------------------------------------
// Elementwise add (float4) — used once for xp0 = src + pos
// ---------------------------------------------------------------------------
__global__ void add_kernel(float* __restrict__ out, const float* __restrict__ a,
                           const float* __restrict__ b, int n4) {
    int i = blockIdx.x * blockDim.x + threadIdx.x;
    if (i < n4) {
        float4 av = reinterpret_cast<const float4*>(a)[i];
        float4 bv = reinterpret_cast<const float4*>(b)[i];
        float4 o;
        o.x = av.x + bv.x; o.y = av.y + bv.y;
        o.z = av.z + bv.z; o.w = av.w + bv.w;
        reinterpret_cast<float4*>(out)[i] = o;
    }
}

// ---------------------------------------------------------------------------
// Deformable sampling with inline softmax; v in fp16, off/att fused (stride 384).
// One warp per (token, head); lane = channel.
// ---------------------------------------------------------------------------
__global__ void deform_sample(const __half* __restrict__ vh,
                              const float* __restrict__ oa,
                              const float* __restrict__ ref,
                              float* __restrict__ out) {
    int w = blockIdx.x * 8 + (threadIdx.x >> 5);
    if (w >= NTOK * NHEAD_) return;
    int lane = threadIdx.x & 31;
    int h = w & 7;
    int t = w >> 3;
    int b = t / LQ_;

    float rx = ref[t * 2 + 0];
    float ry = ref[t * 2 + 1];
    const float* op = oa + (size_t)t * 384 + h * 32;
    const float* lp = oa + (size_t)t * 384 + 256 + h * 16;

    // inline softmax over 16 logits (replicated per lane; broadcast loads)
    float e[16];
    float m = -1e30f;
    #pragma unroll
    for (int j = 0; j < 16; j++) { e[j] = lp[j]; m = fmaxf(m, e[j]); }
    float s = 0.f;
    #pragma unroll
    for (int j = 0; j < 16; j++) { e[j] = expf(e[j] - m); s += e[j]; }
    float inv = 1.f / s;

    const int Ws[4]     = {128, 64, 32, 16};
    const int starts[4] = {0, 16384, 20480, 21504};

    float acc = 0.f;
    #pragma unroll
    for (int l = 0; l < 4; l++) {
        const int   W    = Ws[l];
        const float invW = 1.f / (float)W;
        const float Wm1  = (float)(W - 1);
        const __half* vb = vh + ((size_t)(b * LQ_ + starts[l])) * 256 + h * 32 + lane;
        #pragma unroll
        for (int k = 0; k < 4; k++) {
            float ox  = op[l * 8 + k * 2 + 0];
            float oy  = op[l * 8 + k * 2 + 1];
            float wgt = e[l * 4 + k] * inv;
            float x = (rx + ox * invW) * Wm1;
            float y = (ry + oy * invW) * Wm1;
            x = fminf(fmaxf(x, 0.f), Wm1);
            y = fminf(fmaxf(y, 0.f), Wm1);
            float x0f = floorf(x), y0f = floorf(y);
            float wx = x - x0f, wy = y - y0f;
            int x0 = (int)x0f, y0 = (int)y0f;
            int x1 = min(x0 + 1, W - 1);
            int y1 = min(y0 + 1, W - 1);
            const __half* r0 = vb + (size_t)(y0 * W) * 256;
            const __half* r1 = vb + (size_t)(y1 * W) * 256;
            float v00 = __half2float(r0[x0 * 256]);
            float v10 = __half2float(r0[x1 * 256]);
            float v01 = __half2float(r1[x0 * 256]);
            float v11 = __half2float(r1[x1 * 256]);
            float top = v00 + wx * (v10 - v00);
            float bot = v01 + wx * (v11 - v01);
            acc += wgt * (top + wy * (bot - top));
        }
    }
    out[(size_t)t * 256 + h * 32 + lane] = acc;
}

// ---------------------------------------------------------------------------
// LayerNorm( a + b ) over C=256, one warp per row.
// Optionally also writes xp_out = result + pos (fused next-layer add).
// ---------------------------------------------------------------------------
__global__ void ln_kernel(float* __restrict__ out, const float* __restrict__ a,
                          const float* __restrict__ b, const float* __restrict__ gm,
                          const float* __restrict__ bt,
                          const float* __restrict__ pos, float* __restrict__ xp_out) {
    int row = blockIdx.x * 8 + (threadIdx.x >> 5);
    if (row >= NTOK) return;
    int lane = threadIdx.x & 31;
    const float* ap = a + (size_t)row * 256;
    const float* bp = b + (size_t)row * 256;

    float vals[8];
    float s = 0.f;
    #pragma unroll
    for (int i = 0; i < 8; i++) {
        vals[i] = ap[lane + i * 32] + bp[lane + i * 32];
        s += vals[i];
    }
    #pragma unroll
    for (int o = 16; o; o >>= 1) s += __shfl_xor_sync(0xffffffffu, s, o);
    float mean = s * (1.f / 256.f);

    float var = 0.f;
    #pragma unroll
    for (int i = 0; i < 8; i++) { float d = vals[i] - mean; var += d * d; }
    #pragma unroll
    for (int o = 16; o; o >>= 1) var += __shfl_xor_sync(0xffffffffu, var, o);
    float rstd = rsqrtf(var * (1.f / 256.f) + 1e-5f);

    #pragma unroll
    for (int i = 0; i < 8; i++) {
        int c = lane + i * 32;
        float r = (vals[i] - mean) * rstd * gm[c] + bt[c];
        out[(size_t)row * 256 + c] = r;
        if (xp_out) xp_out[(size_t)row * 256 + c] = r + pos[(size_t)row * 256 + c];
    }
}

// ---------------------------------------------------------------------------
// Launch
// ---------------------------------------------------------------------------
extern "C" void kernel_launch(void* const* d_in, const int* in_sizes, int n_in,
                              void* d_out, int out_size) {
    const float* src  = (const float*)d_in[0];
    const float* pos  = (const float*)d_in[1];
    const float* ref  = (const float*)d_in[2];
    const float* Woff = (const float*)d_in[3];
    const float* boff = (const float*)d_in[4];
    const float* Wat  = (const float*)d_in[5];
    const float* bat  = (const float*)d_in[6];
    const float* Wv   = (const float*)d_in[7];
    const float* bv   = (const float*)d_in[8];
    const float* Wo   = (const float*)d_in[9];
    const float* bo   = (const float*)d_in[10];
    const float* W1   = (const float*)d_in[11];
    const float* b1   = (const float*)d_in[12];
    const float* W2   = (const float*)d_in[13];
    const float* b2   = (const float*)d_in[14];
    const float* n1s  = (const float*)d_in[15];
    const float* n1b  = (const float*)d_in[16];
    const float* n2s  = (const float*)d_in[17];
    const float* n2b  = (const float*)d_in[18];

    float *x, *xp, *aout, *tmp, *hbuf, *oa, *bcat;
    __half* vh;
    __nv_bfloat16 *wch, *wcl, *woh, *wol, *w1h, *w1l, *w2h, *w2l;
    cudaGetSymbolAddress((void**)&x,    g_x);
    cudaGetSymbolAddress((void**)&xp,   g_xp);
    cudaGetSymbolAddress((void**)&aout, g_aout);
    cudaGetSymbolAddress((void**)&tmp,  g_tmp);
    cudaGetSymbolAddress((void**)&hbuf, g_h);
    cudaGetSymbolAddress((void**)&vh,   g_vh);
    cudaGetSymbolAddress((void**)&oa,   g_oa);
    cudaGetSymbolAddress((void**)&bcat, g_bcat);
    cudaGetSymbolAddress((void**)&wch,  g_wcat_h);
    cudaGetSymbolAddress((void**)&wcl,  g_wcat_l);
    cudaGetSymbolAddress((void**)&woh,  g_wo_h);
    cudaGetSymbolAddress((void**)&wol,  g_wo_l);
    cudaGetSymbolAddress((void**)&w1h,  g_w1_h);
    cudaGetSymbolAddress((void**)&w1l,  g_w1_l);
    cudaGetSymbolAddress((void**)&w2h,  g_w2_h);
    cudaGetSymbolAddress((void**)&w2l,  g_w2_l);

    size_t shm = 2 * STAGE_BYTES;
    cudaFuncSetAttribute(gemm_mma<0>, cudaFuncAttributeMaxDynamicSharedMemorySize, (int)shm);
    cudaFuncSetAttribute(gemm_mma<1>, cudaFuncAttributeMaxDynamicSharedMemorySize, (int)shm);
    cudaFuncSetAttribute(gemm_mma<2>, cudaFuncAttributeMaxDynamicSharedMemorySize, (int)shm);

    // ---- one-time weight prep (all layers) ----
    // cat rows: [0,256)=Wv, [256,512)=Woff, [512,640)=Wat ; dst row stride K=256
    prep_w<<<dim3(8, 8, NL_), dim3(32, 8)>>>(Wv,   wch,             wcl,             256, 256,
                                             (size_t)256 * 256, (size_t)640 * 256);
    prep_w<<<dim3(8, 8, NL_), dim3(32, 8)>>>(Woff, wch + 256 * 256, wcl + 256 * 256, 256, 256,
                                             (size_t)256 * 256, (size_t)640 * 256);
    prep_w<<<dim3(4, 8, NL_), dim3(32, 8)>>>(Wat,  wch + 512 * 256, wcl + 512 * 256, 256, 128,
                                             (size_t)256 * 128, (size_t)640 * 256);
    prep_w<<<dim3(8, 8, NL_),  dim3(32, 8)>>>(Wo, woh, wol, 256, 256,
                                              (size_t)256 * 256,  (size_t)256 * 256);
    prep_w<<<dim3(32, 8, NL_), dim3(32, 8)>>>(W1, w1h, w1l, 256, 1024,
                                              (size_t)256 * 1024, (size_t)1024 * 256);
    prep_w<<<dim3(8, 32, NL_), dim3(32, 8)>>>(W2, w2h, w2l, 1024, 256,
                                              (size_t)1024 * 256, (size_t)256 * 1024);
    bias_cat<<<(NL_ * 640 + 255) / 256, 256>>>(bv, boff, bat, bcat);

    const int n4 = NTOK * C_ / 4;
    add_kernel<<<(n4 + 255) / 256, 256>>>(xp, src, pos, n4);   // xp0 = src + pos

    dim3 gcat(640 / 128, NTOK / 128);    // (5, 340)
    dim3 g256(256 / 128, NTOK / 128);    // (2, 340)
    dim3 g1024(1024 / 128, NTOK / 128);  // (8, 340)

    for (int i = 0; i < NL_; i++) {
        // fused projection: v (fp16) + off/att (fp32)
        gemm_mma<2><<<gcat, 256, shm>>>(xp, wch + (size_t)i * 640 * 256, wcl + (size_t)i * 640 * 256,
                                        bcat + i * 640, tmp, vh, oa, NTOK, 256, 640);
        // sampling (softmax inlined)
        deform_sample<<<NTOK, 256>>>(vh, oa, ref, aout);
        // output projection + LN1
        gemm_mma<0><<<g256, 256, shm>>>(aout, woh + (size_t)i * 256 * 256, wol + (size_t)i * 256 * 256,
                                        bo + i * 256, tmp, nullptr, nullptr, NTOK, 256, 256);
        ln_kernel<<<NTOK / 8, 256>>>(x, xp, tmp, n1s + i * 256, n1b + i * 256, nullptr, nullptr);
        // FFN + LN2 (fused +pos for next layer's xp)
        gemm_mma<1><<<g1024, 256, shm>>>(x, w1h + (size_t)i * 1024 * 256, w1l + (size_t)i * 1024 * 256,
                                         b1 + i * 1024, hbuf, nullptr, nullptr, NTOK, 256, 1024);
        gemm_mma<0><<<g256, 256, shm>>>(hbuf, w2h + (size_t)i * 256 * 1024, w2l + (size_t)i * 256 * 1024,
                                        b2 + i * 256, tmp, nullptr, nullptr, NTOK, 1024, 256);
        bool last = (i == NL_ - 1);
        ln_kernel<<<NTOK / 8, 256>>>(last ? (float*)d_out : x, x, tmp,
                                     n2s + i * 256, n2b + i * 256,
                                     last ? nullptr : pos, last ? nullptr : xp);
    }
}